// round 1
// baseline (speedup 1.0000x reference)
#include <cuda_runtime.h>

// Problem constants (shapes fixed by the dataset)
#define NMAX 50000
#define EMAX 800000

// ---------------- scratch (static device allocations; no cudaMalloc) ----------------
__device__ float g_xs[(size_t)NMAX * 128];   // dinv-scaled gathered embeddings
__device__ float g_a [(size_t)NMAX * 128];   // aggregated layer-1 input  (ÂX)
__device__ float g_x1[(size_t)NMAX * 256];   // layer-1 output (post ReLU+LN)
__device__ float g_h2[(size_t)NMAX * 128];   // layer-2 transformed, dinv-scaled
__device__ float g_dinv[NMAX];
__device__ int   g_cnt[NMAX];
__device__ int   g_rowptr[NMAX + 1];
__device__ int   g_fill[NMAX];
__device__ int   g_col[EMAX];
__device__ int   g_part[64];

// ---------------- CSR build ----------------
__global__ void k_zero(int n) {
    int i = blockIdx.x * blockDim.x + threadIdx.x;
    if (i < n) g_cnt[i] = 0;
}

__global__ void k_hist(const int* __restrict__ dst, int E) {
    int i = blockIdx.x * blockDim.x + threadIdx.x;
    if (i < E) atomicAdd(&g_cnt[dst[i]], 1);
}

__global__ void k_scan1(int n) {
    __shared__ int sh[1024];
    int tid = threadIdx.x;
    int i = blockIdx.x * 1024 + tid;
    int v = (i < n) ? g_cnt[i] : 0;
    sh[tid] = v;
    __syncthreads();
    for (int off = 1; off < 1024; off <<= 1) {
        int t = (tid >= off) ? sh[tid - off] : 0;
        __syncthreads();
        sh[tid] += t;
        __syncthreads();
    }
    if (i < n) g_rowptr[i] = sh[tid];       // inclusive scan (temp)
    if (tid == 1023) g_part[blockIdx.x] = sh[1023];
}

__global__ void k_scan2(int nb) {
    // single thread: nb <= 49
    int s = 0;
    for (int b = 0; b < nb; b++) { s += g_part[b]; g_part[b] = s; }
}

__global__ void k_scan3(int n, int E) {
    int tid = threadIdx.x;
    int i = blockIdx.x * 1024 + tid;
    if (i < n) {
        int off = (blockIdx.x > 0) ? g_part[blockIdx.x - 1] : 0;
        int incl = g_rowptr[i] + off;
        int c = g_cnt[i];
        int excl = incl - c;
        g_rowptr[i] = excl;
        g_fill[i] = excl;
        g_dinv[i] = rsqrtf((float)(c + 1));   // +1 self loop
    }
    if (i == 0) g_rowptr[n] = E;
}

__global__ void k_fill(const int* __restrict__ src, const int* __restrict__ dst, int E) {
    int i = blockIdx.x * blockDim.x + threadIdx.x;
    if (i < E) {
        int d = dst[i];
        int pos = atomicAdd(&g_fill[d], 1);
        g_col[pos] = src[i];
    }
}

// ---------------- gather embeddings, pre-scale by dinv ----------------
__global__ void k_gather(const int* __restrict__ xids, const float4* __restrict__ embed, int n) {
    int t = blockIdx.x * blockDim.x + threadIdx.x;
    int i = t >> 5, lane = t & 31;
    if (i >= n) return;
    int id = xids[i];
    float di = g_dinv[i];
    float4 v = embed[(size_t)id * 32 + lane];
    v.x *= di; v.y *= di; v.z *= di; v.w *= di;
    ((float4*)g_xs)[(size_t)i * 32 + lane] = v;
}

// ---------------- aggregation: warp per node, 128 cols (float4/lane) ----------------
// MODE 0: g_xs -> g_a,  out = dinv * (self + sum neighbors)
// MODE 1: g_h2 -> outp, out = LayerNorm(dinv*(self+sum) + b, gamma, beta)
template<int MODE>
__global__ void k_agg(const float* __restrict__ b, const float* __restrict__ gamma,
                      const float* __restrict__ beta, float4* __restrict__ outp, int n) {
    int t = blockIdx.x * blockDim.x + threadIdx.x;
    int w = t >> 5, lane = t & 31;
    if (w >= n) return;
    const float4* xs = (const float4*)(MODE == 0 ? g_xs : g_h2);
    float4 acc = xs[(size_t)w * 32 + lane];   // self message (xs already scaled by dinv[src])
    int s = g_rowptr[w], e = g_rowptr[w + 1];
    for (int b0 = s; b0 < e; b0 += 32) {
        int m = min(32, e - b0);
        int idx = (lane < m) ? g_col[b0 + lane] : 0;
        int tt = 0;
        for (; tt + 4 <= m; tt += 4) {
            int j0 = __shfl_sync(0xffffffffu, idx, tt);
            int j1 = __shfl_sync(0xffffffffu, idx, tt + 1);
            int j2 = __shfl_sync(0xffffffffu, idx, tt + 2);
            int j3 = __shfl_sync(0xffffffffu, idx, tt + 3);
            float4 v0 = xs[(size_t)j0 * 32 + lane];
            float4 v1 = xs[(size_t)j1 * 32 + lane];
            float4 v2 = xs[(size_t)j2 * 32 + lane];
            float4 v3 = xs[(size_t)j3 * 32 + lane];
            acc.x += (v0.x + v1.x) + (v2.x + v3.x);
            acc.y += (v0.y + v1.y) + (v2.y + v3.y);
            acc.z += (v0.z + v1.z) + (v2.z + v3.z);
            acc.w += (v0.w + v1.w) + (v2.w + v3.w);
        }
        for (; tt < m; tt++) {
            int j = __shfl_sync(0xffffffffu, idx, tt);
            float4 v = xs[(size_t)j * 32 + lane];
            acc.x += v.x; acc.y += v.y; acc.z += v.z; acc.w += v.w;
        }
    }
    float di = g_dinv[w];
    if (MODE == 0) {
        float4 o = make_float4(acc.x * di, acc.y * di, acc.z * di, acc.w * di);
        ((float4*)g_a)[(size_t)w * 32 + lane] = o;
    } else {
        float4 bb = ((const float4*)b)[lane];
        float4 y = make_float4(acc.x * di + bb.x, acc.y * di + bb.y,
                               acc.z * di + bb.z, acc.w * di + bb.w);
        float s1 = y.x + y.y + y.z + y.w;
        #pragma unroll
        for (int off = 16; off; off >>= 1) s1 += __shfl_xor_sync(0xffffffffu, s1, off);
        float mu = s1 * (1.0f / 128.0f);
        float dx = y.x - mu, dy = y.y - mu, dz = y.z - mu, dw = y.w - mu;
        float sq = dx * dx + dy * dy + dz * dz + dw * dw;
        #pragma unroll
        for (int off = 16; off; off >>= 1) sq += __shfl_xor_sync(0xffffffffu, sq, off);
        float rstd = rsqrtf(sq * (1.0f / 128.0f) + 1e-5f);
        float4 gg = ((const float4*)gamma)[lane];
        float4 bt = ((const float4*)beta)[lane];
        outp[(size_t)w * 32 + lane] = make_float4(dx * rstd * gg.x + bt.x,
                                                  dy * rstd * gg.y + bt.y,
                                                  dz * rstd * gg.z + bt.z,
                                                  dw * rstd * gg.w + bt.w);
    }
}

// ---------------- GEMM: A[M,K] @ W[K,N], W resident in smem, fused epilogues ----------------
// MODE 0: A=g_a  (K=128), out=g_x1 (N=256), epilogue = +bias, ReLU, LayerNorm(gamma,beta)
// MODE 1: A=g_x1 (K=256), out=g_h2 (N=128), epilogue = * dinv[row]
// Thread layout: 256 threads, tile 32 rows x N cols. tx=lane (0..31), ty=warp (0..7).
// Thread owns rows [4*ty, 4*ty+4) and col-pairs {2*tx + 64*j | j < N/64}.
// Inner loop uses packed fma.rn.f32x2 for 2x fp32 FMA throughput.
template<int K, int N, int MODE>
__global__ void k_gemm(const float* __restrict__ W, const float* __restrict__ bias,
                       const float* __restrict__ gamma, const float* __restrict__ beta,
                       int M) {
    extern __shared__ float smem[];
    float* Ws = smem;             // K*N floats
    float* Xs = smem + K * N;     // 32*K floats
    constexpr int NJ = N / 64;

    const float* A = (MODE == 0) ? g_a : g_x1;
    float* out = (MODE == 0) ? g_x1 : g_h2;

    int tid = threadIdx.x;
    // Load W into smem once (float4 vectorized)
    {
        const float4* Wv = (const float4*)W;
        float4* Wsv = (float4*)Ws;
        for (int idx = tid; idx < K * N / 4; idx += 256) Wsv[idx] = Wv[idx];
    }

    int tx = tid & 31, ty = tid >> 5;

    for (int m0 = blockIdx.x * 32; m0 < M; m0 += gridDim.x * 32) {
        __syncthreads();  // previous tile compute done (and W load visible, first iter)
        // Load X tile (32 rows x K)
        for (int idx = tid; idx < 32 * (K / 4); idx += 256) {
            int r = idx / (K / 4), kk = idx % (K / 4);
            int row = m0 + r;
            float4 v = (row < M) ? ((const float4*)A)[(size_t)row * (K / 4) + kk]
                                 : make_float4(0.f, 0.f, 0.f, 0.f);
            ((float4*)Xs)[idx] = v;
        }
        __syncthreads();

        unsigned long long acc[4][NJ];
        #pragma unroll
        for (int q = 0; q < 4; q++)
            #pragma unroll
            for (int j = 0; j < NJ; j++) acc[q][j] = 0ull;

        const float* xr = Xs + (ty * 4) * K;
        #pragma unroll 4
        for (int k = 0; k < K; k++) {
            unsigned long long w2[NJ];
            #pragma unroll
            for (int j = 0; j < NJ; j++)
                w2[j] = *reinterpret_cast<const unsigned long long*>(Ws + k * N + 2 * tx + 64 * j);
            #pragma unroll
            for (int q = 0; q < 4; q++) {
                unsigned xu = __float_as_uint(xr[q * K + k]);
                unsigned long long x2;
                asm("mov.b64 %0, {%1, %1};" : "=l"(x2) : "r"(xu));
                #pragma unroll
                for (int j = 0; j < NJ; j++)
                    asm("fma.rn.f32x2 %0, %1, %2, %0;" : "+l"(acc[q][j]) : "l"(x2), "l"(w2[j]));
            }
        }

        // Unpack accumulators
        float v[4][2 * NJ];
        #pragma unroll
        for (int q = 0; q < 4; q++)
            #pragma unroll
            for (int j = 0; j < NJ; j++) {
                unsigned u0, u1;
                asm("mov.b64 {%0, %1}, %2;" : "=r"(u0), "=r"(u1) : "l"(acc[q][j]));
                v[q][2 * j] = __uint_as_float(u0);
                v[q][2 * j + 1] = __uint_as_float(u1);
            }

        if (MODE == 0) {
            // bias + relu
            #pragma unroll
            for (int j = 0; j < NJ; j++) {
                int c = 2 * tx + 64 * j;
                float2 bb = *(const float2*)(bias + c);
                #pragma unroll
                for (int q = 0; q < 4; q++) {
                    v[q][2 * j]     = fmaxf(v[q][2 * j] + bb.x, 0.f);
                    v[q][2 * j + 1] = fmaxf(v[q][2 * j + 1] + bb.y, 0.f);
                }
            }
            // LayerNorm per row; each warp owns 4 full rows
            float s[4], mu[4], rstd[4];
            #pragma unroll
            for (int q = 0; q < 4; q++) {
                float t = 0.f;
                #pragma unroll
                for (int jj = 0; jj < 2 * NJ; jj++) t += v[q][jj];
                s[q] = t;
            }
            #pragma unroll
            for (int off = 16; off; off >>= 1)
                #pragma unroll
                for (int q = 0; q < 4; q++) s[q] += __shfl_xor_sync(0xffffffffu, s[q], off);
            #pragma unroll
            for (int q = 0; q < 4; q++) mu[q] = s[q] * (1.0f / N);
            #pragma unroll
            for (int q = 0; q < 4; q++) {
                float t = 0.f;
                #pragma unroll
                for (int jj = 0; jj < 2 * NJ; jj++) {
                    float d = v[q][jj] - mu[q];
                    t += d * d;
                }
                s[q] = t;
            }
            #pragma unroll
            for (int off = 16; off; off >>= 1)
                #pragma unroll
                for (int q = 0; q < 4; q++) s[q] += __shfl_xor_sync(0xffffffffu, s[q], off);
            #pragma unroll
            for (int q = 0; q < 4; q++) rstd[q] = rsqrtf(s[q] * (1.0f / N) + 1e-5f);

            #pragma unroll
            for (int q = 0; q < 4; q++) {
                int row = m0 + ty * 4 + q;
                if (row < M) {
                    #pragma unroll
                    for (int j = 0; j < NJ; j++) {
                        int c = 2 * tx + 64 * j;
                        float2 gg = *(const float2*)(gamma + c);
                        float2 bt = *(const float2*)(beta + c);
                        float2 o;
                        o.x = (v[q][2 * j] - mu[q]) * rstd[q] * gg.x + bt.x;
                        o.y = (v[q][2 * j + 1] - mu[q]) * rstd[q] * gg.y + bt.y;
                        *(float2*)(out + (size_t)row * N + c) = o;
                    }
                }
            }
        } else {
            #pragma unroll
            for (int q = 0; q < 4; q++) {
                int row = m0 + ty * 4 + q;
                if (row < M) {
                    float di = g_dinv[row];
                    #pragma unroll
                    for (int j = 0; j < NJ; j++) {
                        int c = 2 * tx + 64 * j;
                        float2 o;
                        o.x = v[q][2 * j] * di;
                        o.y = v[q][2 * j + 1] * di;
                        *(float2*)(out + (size_t)row * N + c) = o;
                    }
                }
            }
        }
    }
}

// ---------------- launch ----------------
extern "C" void kernel_launch(void* const* d_in, const int* in_sizes, int n_in,
                              void* d_out, int out_size) {
    const int*   x_ids = (const int*)d_in[0];
    const int*   ei    = (const int*)d_in[1];
    const float* embed = (const float*)d_in[2];
    const float* W1    = (const float*)d_in[3];
    const float* b1    = (const float*)d_in[4];
    const float* g1    = (const float*)d_in[5];
    const float* be1   = (const float*)d_in[6];
    const float* W2    = (const float*)d_in[7];
    const float* b2    = (const float*)d_in[8];
    const float* g2    = (const float*)d_in[9];
    const float* be2   = (const float*)d_in[10];
    float* out = (float*)d_out;

    int n = in_sizes[0];        // 50000
    int E = in_sizes[1] / 2;    // 800000
    const int* src = ei;
    const int* dst = ei + E;

    const int smem1 = (128 * 256 + 32 * 128) * (int)sizeof(float);   // 147456
    const int smem2 = (256 * 128 + 32 * 256) * (int)sizeof(float);   // 163840
    cudaFuncSetAttribute((const void*)k_gemm<128, 256, 0>,
                         cudaFuncAttributeMaxDynamicSharedMemorySize, smem1);
    cudaFuncSetAttribute((const void*)k_gemm<256, 128, 1>,
                         cudaFuncAttributeMaxDynamicSharedMemorySize, smem2);

    int nb = (n + 1023) / 1024;

    k_zero<<<(n + 255) / 256, 256>>>(n);
    k_hist<<<(E + 255) / 256, 256>>>(dst, E);
    k_scan1<<<nb, 1024>>>(n);
    k_scan2<<<1, 1>>>(nb);
    k_scan3<<<nb, 1024>>>(n, E);
    k_fill<<<(E + 255) / 256, 256>>>(src, dst, E);

    int warps_grid = (n * 32 + 255) / 256;
    k_gather<<<warps_grid, 256>>>(x_ids, (const float4*)embed, n);

    // Layer 1: aggregate first (128 cols), then GEMM 128->256 with fused bias+ReLU+LN
    k_agg<0><<<warps_grid, 256>>>(nullptr, nullptr, nullptr, nullptr, n);
    k_gemm<128, 256, 0><<<152, 256, smem1>>>(W1, b1, g1, be1, n);

    // Layer 2: GEMM 256->128 with fused dinv scaling, then aggregate + bias + LN
    k_gemm<256, 128, 1><<<152, 256, smem2>>>(W2, nullptr, nullptr, nullptr, n);
    k_agg<1><<<warps_grid, 256>>>(b2, g2, be2, (float4*)out, n);
}